// round 1
// baseline (speedup 1.0000x reference)
#include <cuda_runtime.h>
#include <cuda_bf16.h>

#define N_NODES 100000
#define N_EDGES 1600000
#define D 32
#define ED 8

// Scratch (ping-pong node features + aggregation buffer). Static __device__
// globals per the no-allocation rules.
__device__ float g_buf0[N_NODES * D];
__device__ float g_buf1[N_NODES * D];
__device__ float g_agg[N_NODES * D];

// ---------------------------------------------------------------------------
// Zero the aggregation buffer (float4 vectorized grid-stride).
// ---------------------------------------------------------------------------
__global__ void zero_agg_kernel() {
    const int n4 = N_NODES * D / 4;
    float4* p = reinterpret_cast<float4*>(g_agg);
    float4 z = make_float4(0.f, 0.f, 0.f, 0.f);
    for (int i = blockIdx.x * blockDim.x + threadIdx.x; i < n4;
         i += gridDim.x * blockDim.x) {
        p[i] = z;
    }
}

// ---------------------------------------------------------------------------
// Edge kernel: one warp per edge, lane = output column j (0..31).
//   e_j   = be[j] + sum_k edge_attr[e][k] * We[k][j]
//   msg_j = relu(x[src][j] + e_j)
//   atomicAdd(agg[dst][j], msg_j)
// We[l] column j lives in 8 registers per lane (loaded once per thread).
// edge_attr: lanes read ea[e*8 + (lane&7)] -> one 32B-sector broadcast load,
// then 8 SHFLs distribute the 8 attrs to every lane.
// ---------------------------------------------------------------------------
__global__ __launch_bounds__(256) void edge_kernel(
    const float* __restrict__ x_ext, int x_sel,
    const float* __restrict__ edge_attr,
    const float* __restrict__ We,   // layer slice: [8, 32]
    const float* __restrict__ be,   // layer slice: [32]
    const int*   __restrict__ src,
    const int*   __restrict__ dst)
{
    const float* x = (x_sel == 0) ? x_ext : (x_sel == 1 ? g_buf0 : g_buf1);

    const int lane   = threadIdx.x & 31;
    const int wid    = (blockIdx.x * blockDim.x + threadIdx.x) >> 5;
    const int nwarps = (gridDim.x * blockDim.x) >> 5;

    float w[ED];
#pragma unroll
    for (int k = 0; k < ED; k++) w[k] = We[k * D + lane];
    const float bias = be[lane];

    for (int e = wid; e < N_EDGES; e += nwarps) {
        const int s = __ldg(src + e);
        const int d = __ldg(dst + e);
        const float av = __ldg(edge_attr + e * ED + (lane & 7));

        float acc = bias;
#pragma unroll
        for (int k = 0; k < ED; k++)
            acc = fmaf(__shfl_sync(0xffffffffu, av, k), w[k], acc);

        const float xv = __ldg(x + s * D + lane);  // coalesced 128B row
        const float m  = fmaxf(xv + acc, 0.0f);
        atomicAdd(g_agg + d * D + lane, m);
    }
}

// ---------------------------------------------------------------------------
// Node kernel: one warp per node, lane = output column j.
//   h_k  = x[node][k] + agg[node][k]
//   o_j  = leaky_relu(b[j] + sum_k h_k * W[k][j])
// W[l] column j in 32 registers per lane; h distributed via SHFL.
// ---------------------------------------------------------------------------
__global__ __launch_bounds__(256) void node_kernel(
    const float* __restrict__ x_ext, int x_sel,
    float* __restrict__ out_ext, int out_sel,
    const float* __restrict__ W,    // layer slice: [32, 32]
    const float* __restrict__ b)    // layer slice: [32]
{
    const float* x  = (x_sel == 0) ? x_ext : (x_sel == 1 ? g_buf0 : g_buf1);
    float* out = (out_sel == 0) ? out_ext : (out_sel == 1 ? g_buf0 : g_buf1);

    const int lane   = threadIdx.x & 31;
    const int wid    = (blockIdx.x * blockDim.x + threadIdx.x) >> 5;
    const int nwarps = (gridDim.x * blockDim.x) >> 5;

    float w[D];
#pragma unroll
    for (int k = 0; k < D; k++) w[k] = W[k * D + lane];
    const float bias = b[lane];

    for (int node = wid; node < N_NODES; node += nwarps) {
        const float h = x[node * D + lane] + g_agg[node * D + lane];
        float acc = bias;
#pragma unroll
        for (int k = 0; k < D; k++)
            acc = fmaf(__shfl_sync(0xffffffffu, h, k), w[k], acc);
        out[node * D + lane] = fmaxf(acc, 0.01f * acc);  // leaky_relu, slope 0.01
    }
}

// ---------------------------------------------------------------------------
// Launch: 3 layers of { zero agg; edge scatter; node transform }.
// Ping-pong: ext -> g_buf0 -> g_buf1 -> d_out.
// ---------------------------------------------------------------------------
extern "C" void kernel_launch(void* const* d_in, const int* in_sizes, int n_in,
                              void* d_out, int out_size)
{
    const float* x   = (const float*)d_in[0];   // [N, 32]
    const float* ea  = (const float*)d_in[1];   // [E, 8]
    const float* W   = (const float*)d_in[2];   // [3, 32, 32]
    const float* b   = (const float*)d_in[3];   // [3, 32]
    const float* We  = (const float*)d_in[4];   // [3, 8, 32]
    const float* be  = (const float*)d_in[5];   // [3, 32]
    const int*   ei  = (const int*)d_in[6];     // [2, E] int32
    float* out = (float*)d_out;

    const int* src = ei;
    const int* dst = ei + N_EDGES;

    // Layer l: x_sel[l] selects input buffer, out_sel[l] output buffer.
    // 0 = external pointer, 1 = g_buf0, 2 = g_buf1.
    const int x_sels[3]   = {0, 1, 2};
    const int out_sels[3] = {1, 2, 0};

    const int edge_blocks = 1184;   // 148 SMs * 8
    const int node_blocks = 592;
    const int zero_blocks = 1184;

    for (int l = 0; l < 3; l++) {
        zero_agg_kernel<<<zero_blocks, 256>>>();
        edge_kernel<<<edge_blocks, 256>>>(
            x, x_sels[l], ea, We + l * ED * D, be + l * D, src, dst);
        node_kernel<<<node_blocks, 256>>>(
            x, x_sels[l], out, out_sels[l], W + l * D * D, b + l * D);
    }
}